// round 1
// baseline (speedup 1.0000x reference)
#include <cuda_runtime.h>

#define TPB 128      // threads per block == targets per block
#define SCHUNK 32    // sources handled per block (grid.y splits S)
#define NS 4         // sources processed together per thread (amortize weight LDS)

struct __align__(16) SrcData {
    float x, y, z, area;       // coords pre-scaled by 1/refL
    float logn, nhx, nhy, nhz; // 0.5*ln(n2), unit normal
    float w, pad0, pad1, pad2; // strength
};

__global__ void __launch_bounds__(256) zero_kernel(float* out, int n) {
    int i = blockIdx.x * blockDim.x + threadIdx.x;
    if (i < n) out[i] = 0.0f;
}

__global__ void __launch_bounds__(TPB) bh_kernel(
    const float* __restrict__ refL,
    const float* __restrict__ sp,
    const float* __restrict__ tp,
    const float* __restrict__ ss,
    const float* __restrict__ sa,
    const float* __restrict__ sn,
    const float* __restrict__ W1,
    const float* __restrict__ b1,
    const float* __restrict__ W2,
    const float* __restrict__ b2,
    float* __restrict__ out,
    int T, int S)
{
    __shared__ float sW1[7][64];
    __shared__ float sb1[64];
    __shared__ float sW2[64][4];
    __shared__ float sb2[4];
    __shared__ SrcData ssrc[SCHUNK];

    const int tid = threadIdx.x;
    const float invL = 1.0f / refL[0];

    for (int i = tid; i < 7 * 64; i += TPB) sW1[i / 64][i % 64] = W1[i];
    for (int i = tid; i < 64; i += TPB)      sb1[i] = b1[i];
    for (int i = tid; i < 64 * 4; i += TPB)  sW2[i / 4][i % 4] = W2[i];
    if (tid < 4) sb2[tid] = b2[tid];

    const int s0 = blockIdx.y * SCHUNK;
    if (tid < SCHUNK) {
        int s = s0 + tid;
        SrcData d;
        if (s < S) {
            float nx = sn[3 * s], ny = sn[3 * s + 1], nz = sn[3 * s + 2];
            float n2 = fmaf(nx, nx, fmaf(ny, ny, nz * nz)) + 1e-16f;
            float invn = rsqrtf(n2);
            d.x = sp[3 * s] * invL;
            d.y = sp[3 * s + 1] * invL;
            d.z = sp[3 * s + 2] * invL;
            d.area = sa[s];
            d.logn = 0.5f * __logf(n2);
            d.nhx = nx * invn; d.nhy = ny * invn; d.nhz = nz * invn;
            d.w = ss[s];
        } else {
            d.x = 0.f; d.y = 0.f; d.z = 0.f; d.area = 0.f;
            d.logn = 0.f; d.nhx = 1.f; d.nhy = 0.f; d.nhz = 0.f;
            d.w = 0.f;  // zero strength -> no contribution
        }
        d.pad0 = d.pad1 = d.pad2 = 0.f;
        ssrc[tid] = d;
    }
    __syncthreads();

    const int t = blockIdx.x * TPB + tid;
    if (t >= T) return;

    const float tx = tp[3 * t] * invL;
    const float ty = tp[3 * t + 1] * invL;
    const float tz = tp[3 * t + 2] * invL;

    float acc0 = 0.f, acc1 = 0.f, acc2 = 0.f, acc3 = 0.f;

    #pragma unroll 1
    for (int sb = 0; sb < SCHUNK; sb += NS) {
        // Front: per-source features into registers
        float f0[NS], f1[NS], f2[NS], f3[NS], f4[NS], f5[NS], f6[NS];
        float rx[NS], ry[NS], rz[NS], ir[NS];
        float o0[NS], o1[NS], o2[NS], o3[NS];
        #pragma unroll
        for (int u = 0; u < NS; u++) {
            const SrcData sd = ssrc[sb + u];
            float dx = tx - sd.x, dy = ty - sd.y, dz = tz - sd.z;
            float r2 = fmaf(dx, dx, fmaf(dy, dy, dz * dz)) + 1e-16f;
            float irr = rsqrtf(r2);
            float c = (dx * sd.nhx + dy * sd.nhy + dz * sd.nhz) * irr;
            float c2 = c * c;
            f0[u] = sd.area;
            f1[u] = 0.5f * __logf(r2);
            f2[u] = sd.logn;
            f3[u] = c;
            f4[u] = fmaf(1.5f, c2, -0.5f);
            f5[u] = fmaf(2.5f, c2, -1.5f) * c;
            f6[u] = fmaf(fmaf(4.375f, c2, -3.75f), c2, 0.375f);
            rx[u] = dx; ry[u] = dy; rz[u] = dz; ir[u] = irr;
            o0[u] = sb2[0]; o1[u] = sb2[1]; o2[u] = sb2[2]; o3[u] = sb2[3];
        }

        // Fused MLP: per hidden unit j, load its weight column once,
        // apply to NS feature sets (weight LDS amortized 4x)
        #pragma unroll 4
        for (int j = 0; j < 64; j++) {
            float w0 = sW1[0][j], w1 = sW1[1][j], w2 = sW1[2][j], w3 = sW1[3][j];
            float w4 = sW1[4][j], w5 = sW1[5][j], w6 = sW1[6][j];
            float bj = sb1[j];
            float v0 = sW2[j][0], v1 = sW2[j][1], v2 = sW2[j][2], v3 = sW2[j][3];
            #pragma unroll
            for (int u = 0; u < NS; u++) {
                float a = bj;
                a = fmaf(f0[u], w0, a);
                a = fmaf(f1[u], w1, a);
                a = fmaf(f2[u], w2, a);
                a = fmaf(f3[u], w3, a);
                a = fmaf(f4[u], w4, a);
                a = fmaf(f5[u], w5, a);
                a = fmaf(f6[u], w6, a);
                // silu(a) = a / (1 + exp(-a))
                float h = __fdividef(a, 1.0f + __expf(-a));
                o0[u] = fmaf(h, v0, o0[u]);
                o1[u] = fmaf(h, v1, o1[u]);
                o2[u] = fmaf(h, v2, o2[u]);
                o3[u] = fmaf(h, v3, o3[u]);
            }
        }

        // Epilogue: tanh, decay weighting, accumulate
        #pragma unroll
        for (int u = 0; u < NS; u++) {
            const SrcData sd = ssrc[sb + u];
            float t0 = tanhf(o0[u]);
            float t1 = tanhf(o1[u]);
            float t2 = tanhf(o2[u]);
            float t3 = tanhf(o3[u]);
            float irr = ir[u];
            float wir = sd.w * irr;              // w * inv_r   (scalar decay, D=3)
            acc0 = fmaf(wir, t0, acc0);
            float wv = wir * irr;                // w * inv_r^2 (vector decay)
            float rhx = rx[u] * irr, rhy = ry[u] * irr, rhz = rz[u] * irr;
            float cx = rhy * sd.nhz - rhz * sd.nhy;
            float cy = rhz * sd.nhx - rhx * sd.nhz;
            float cz = rhx * sd.nhy - rhy * sd.nhx;
            acc1 = fmaf(wv, fmaf(t1, rhx, fmaf(t2, sd.nhx, t3 * cx)), acc1);
            acc2 = fmaf(wv, fmaf(t1, rhy, fmaf(t2, sd.nhy, t3 * cy)), acc2);
            acc3 = fmaf(wv, fmaf(t1, rhz, fmaf(t2, sd.nhz, t3 * cz)), acc3);
        }
    }

    atomicAdd(&out[4 * t + 0], acc0);
    atomicAdd(&out[4 * t + 1], acc1);
    atomicAdd(&out[4 * t + 2], acc2);
    atomicAdd(&out[4 * t + 3], acc3);
}

extern "C" void kernel_launch(void* const* d_in, const int* in_sizes, int n_in,
                              void* d_out, int out_size) {
    const float* refL = (const float*)d_in[0];
    const float* sp   = (const float*)d_in[1];
    const float* tp   = (const float*)d_in[2];
    const float* ss   = (const float*)d_in[3];
    const float* sa   = (const float*)d_in[4];
    const float* sn   = (const float*)d_in[5];
    const float* W1   = (const float*)d_in[6];
    const float* b1   = (const float*)d_in[7];
    const float* W2   = (const float*)d_in[8];
    const float* b2   = (const float*)d_in[9];
    float* out = (float*)d_out;

    int S = in_sizes[3];          // source_strengths element count
    int T = in_sizes[2] / 3;      // target_points is (T, 3)

    zero_kernel<<<(out_size + 255) / 256, 256>>>(out, out_size);

    dim3 grid((T + TPB - 1) / TPB, (S + SCHUNK - 1) / SCHUNK);
    bh_kernel<<<grid, TPB>>>(refL, sp, tp, ss, sa, sn, W1, b1, W2, b2, out, T, S);
}

// round 2
// speedup vs baseline: 1.0294x; 1.0294x over previous
#include <cuda_runtime.h>

#define TPB 128      // threads per block == targets per block
#define SCHUNK 32    // sources handled per block (grid.y splits S)
#define NS 4         // sources per thread-iteration = 2 packed f32x2 lanes

typedef unsigned long long ull;

__device__ __forceinline__ ull pack2(float lo, float hi) {
    ull r; asm("mov.b64 %0, {%1, %2};" : "=l"(r) : "f"(lo), "f"(hi)); return r;
}
__device__ __forceinline__ void unpack2(ull v, float& lo, float& hi) {
    asm("mov.b64 {%0, %1}, %2;" : "=f"(lo), "=f"(hi) : "l"(v));
}
__device__ __forceinline__ ull fma2(ull a, ull b, ull c) {
    ull d; asm("fma.rn.f32x2 %0, %1, %2, %3;" : "=l"(d) : "l"(a), "l"(b), "l"(c)); return d;
}
__device__ __forceinline__ ull mul2(ull a, ull b) {
    ull d; asm("mul.rn.f32x2 %0, %1, %2;" : "=l"(d) : "l"(a), "l"(b)); return d;
}
__device__ __forceinline__ float tanh_apx(float x) {
    float y; asm("tanh.approx.f32 %0, %1;" : "=f"(y) : "f"(x)); return y;
}
// silu(a) = a*sigmoid(a) = b + b*tanh(b), b = a/2   (packed, 2 MUFU.TANH)
__device__ __forceinline__ ull silu2(ull a, ull halfp) {
    ull b = mul2(a, halfp);
    float blo, bhi; unpack2(b, blo, bhi);
    ull t = pack2(tanh_apx(blo), tanh_apx(bhi));
    return fma2(b, t, b);
}
// accurate-enough scalar tanh for the epilogue: 1 - 2/(exp(2x)+1)
__device__ __forceinline__ float tanh_fast(float x) {
    float e = __expf(2.0f * x);
    return 1.0f - __fdividef(2.0f, e + 1.0f);
}

struct __align__(16) SrcData {
    float x, y, z, area;       // coords pre-scaled by 1/refL
    float logn, nhx, nhy, nhz; // 0.5*ln(n2), unit normal
    float w, pad0, pad1, pad2; // strength
};

__global__ void __launch_bounds__(256) zero_kernel(float* out, int n) {
    int i = blockIdx.x * blockDim.x + threadIdx.x;
    if (i < n) out[i] = 0.0f;
}

__global__ void __launch_bounds__(TPB) bh_kernel(
    const float* __restrict__ refL,
    const float* __restrict__ sp,
    const float* __restrict__ tp,
    const float* __restrict__ ss,
    const float* __restrict__ sa,
    const float* __restrict__ sn,
    const float* __restrict__ W1,
    const float* __restrict__ b1,
    const float* __restrict__ W2,
    const float* __restrict__ b2,
    float* __restrict__ out,
    int T, int S)
{
    // weights duplicated into both halves of a 64-bit word: one LDS.64
    // broadcast feeds a packed fma.rn.f32x2 directly (no pack instrs).
    __shared__ ull sW1d[7][64];
    __shared__ ull sb1d[64];
    __shared__ ull sW2d[64][4];
    __shared__ ull sb2d[4];
    __shared__ SrcData ssrc[SCHUNK];

    const int tid = threadIdx.x;
    const float invL = 1.0f / refL[0];

    for (int i = tid; i < 7 * 64; i += TPB) { float w = W1[i]; sW1d[i / 64][i % 64] = pack2(w, w); }
    for (int i = tid; i < 64; i += TPB)      { float w = b1[i]; sb1d[i] = pack2(w, w); }
    for (int i = tid; i < 64 * 4; i += TPB)  { float w = W2[i]; sW2d[i / 4][i % 4] = pack2(w, w); }
    if (tid < 4) { float w = b2[tid]; sb2d[tid] = pack2(w, w); }

    const int s0 = blockIdx.y * SCHUNK;
    if (tid < SCHUNK) {
        int s = s0 + tid;
        SrcData d;
        if (s < S) {
            float nx = sn[3 * s], ny = sn[3 * s + 1], nz = sn[3 * s + 2];
            float n2 = fmaf(nx, nx, fmaf(ny, ny, nz * nz)) + 1e-16f;
            float invn = rsqrtf(n2);
            d.x = sp[3 * s] * invL;
            d.y = sp[3 * s + 1] * invL;
            d.z = sp[3 * s + 2] * invL;
            d.area = sa[s];
            d.logn = 0.5f * __logf(n2);
            d.nhx = nx * invn; d.nhy = ny * invn; d.nhz = nz * invn;
            d.w = ss[s];
        } else {
            d.x = 0.f; d.y = 0.f; d.z = 0.f; d.area = 0.f;
            d.logn = 0.f; d.nhx = 1.f; d.nhy = 0.f; d.nhz = 0.f;
            d.w = 0.f;  // zero strength -> no contribution
        }
        d.pad0 = d.pad1 = d.pad2 = 0.f;
        ssrc[tid] = d;
    }
    __syncthreads();

    const int t = blockIdx.x * TPB + tid;
    if (t >= T) return;

    const float tx = tp[3 * t] * invL;
    const float ty = tp[3 * t + 1] * invL;
    const float tz = tp[3 * t + 2] * invL;

    const ull halfp = pack2(0.5f, 0.5f);

    float acc0 = 0.f, acc1 = 0.f, acc2 = 0.f, acc3 = 0.f;

    #pragma unroll 1
    for (int sb = 0; sb < SCHUNK; sb += NS) {
        // ---- front: per-source features (scalar), then pack into 2 lanes
        float f0[NS], f1[NS], f2[NS], f3[NS], f4[NS], f5[NS], f6[NS];
        float rx[NS], ry[NS], rz[NS], ir[NS];
        #pragma unroll
        for (int u = 0; u < NS; u++) {
            const SrcData sd = ssrc[sb + u];
            float dx = tx - sd.x, dy = ty - sd.y, dz = tz - sd.z;
            float r2 = fmaf(dx, dx, fmaf(dy, dy, dz * dz)) + 1e-16f;
            float irr = rsqrtf(r2);
            float c = (dx * sd.nhx + dy * sd.nhy + dz * sd.nhz) * irr;
            float c2 = c * c;
            f0[u] = sd.area;
            f1[u] = 0.5f * __logf(r2);
            f2[u] = sd.logn;
            f3[u] = c;
            f4[u] = fmaf(1.5f, c2, -0.5f);
            f5[u] = fmaf(2.5f, c2, -1.5f) * c;
            f6[u] = fmaf(fmaf(4.375f, c2, -3.75f), c2, 0.375f);
            rx[u] = dx; ry[u] = dy; rz[u] = dz; ir[u] = irr;
        }
        ull F0[2], F1[2], F2[2], F3[2], F4[2], F5[2], F6[2];
        ull O0[2], O1[2], O2[2], O3[2];
        #pragma unroll
        for (int l = 0; l < 2; l++) {
            F0[l] = pack2(f0[2*l], f0[2*l+1]);
            F1[l] = pack2(f1[2*l], f1[2*l+1]);
            F2[l] = pack2(f2[2*l], f2[2*l+1]);
            F3[l] = pack2(f3[2*l], f3[2*l+1]);
            F4[l] = pack2(f4[2*l], f4[2*l+1]);
            F5[l] = pack2(f5[2*l], f5[2*l+1]);
            F6[l] = pack2(f6[2*l], f6[2*l+1]);
            O0[l] = sb2d[0]; O1[l] = sb2d[1]; O2[l] = sb2d[2]; O3[l] = sb2d[3];
        }

        // ---- fused MLP: packed f32x2 FMAs, weights broadcast via LDS.64
        #pragma unroll 2
        for (int j = 0; j < 64; j++) {
            ull w0 = sW1d[0][j], w1 = sW1d[1][j], w2 = sW1d[2][j], w3 = sW1d[3][j];
            ull w4 = sW1d[4][j], w5 = sW1d[5][j], w6 = sW1d[6][j];
            ull bj = sb1d[j];
            ull v0 = sW2d[j][0], v1 = sW2d[j][1], v2 = sW2d[j][2], v3 = sW2d[j][3];
            #pragma unroll
            for (int l = 0; l < 2; l++) {
                ull a = bj;
                a = fma2(F0[l], w0, a);
                a = fma2(F1[l], w1, a);
                a = fma2(F2[l], w2, a);
                a = fma2(F3[l], w3, a);
                a = fma2(F4[l], w4, a);
                a = fma2(F5[l], w5, a);
                a = fma2(F6[l], w6, a);
                ull h = silu2(a, halfp);
                O0[l] = fma2(h, v0, O0[l]);
                O1[l] = fma2(h, v1, O1[l]);
                O2[l] = fma2(h, v2, O2[l]);
                O3[l] = fma2(h, v3, O3[l]);
            }
        }

        // ---- epilogue: tanh, decay weighting, accumulate
        float o0[NS], o1[NS], o2[NS], o3[NS];
        unpack2(O0[0], o0[0], o0[1]); unpack2(O0[1], o0[2], o0[3]);
        unpack2(O1[0], o1[0], o1[1]); unpack2(O1[1], o1[2], o1[3]);
        unpack2(O2[0], o2[0], o2[1]); unpack2(O2[1], o2[2], o2[3]);
        unpack2(O3[0], o3[0], o3[1]); unpack2(O3[1], o3[2], o3[3]);
        #pragma unroll
        for (int u = 0; u < NS; u++) {
            const SrcData sd = ssrc[sb + u];
            float t0 = tanh_fast(o0[u]);
            float t1 = tanh_fast(o1[u]);
            float t2 = tanh_fast(o2[u]);
            float t3 = tanh_fast(o3[u]);
            float irr = ir[u];
            float wir = sd.w * irr;              // w * inv_r   (scalar decay, D=3)
            acc0 = fmaf(wir, t0, acc0);
            float wv = wir * irr;                // w * inv_r^2 (vector decay)
            float rhx = rx[u] * irr, rhy = ry[u] * irr, rhz = rz[u] * irr;
            float cx = rhy * sd.nhz - rhz * sd.nhy;
            float cy = rhz * sd.nhx - rhx * sd.nhz;
            float cz = rhx * sd.nhy - rhy * sd.nhx;
            acc1 = fmaf(wv, fmaf(t1, rhx, fmaf(t2, sd.nhx, t3 * cx)), acc1);
            acc2 = fmaf(wv, fmaf(t1, rhy, fmaf(t2, sd.nhy, t3 * cy)), acc2);
            acc3 = fmaf(wv, fmaf(t1, rhz, fmaf(t2, sd.nhz, t3 * cz)), acc3);
        }
    }

    atomicAdd(&out[4 * t + 0], acc0);
    atomicAdd(&out[4 * t + 1], acc1);
    atomicAdd(&out[4 * t + 2], acc2);
    atomicAdd(&out[4 * t + 3], acc3);
}

extern "C" void kernel_launch(void* const* d_in, const int* in_sizes, int n_in,
                              void* d_out, int out_size) {
    const float* refL = (const float*)d_in[0];
    const float* sp   = (const float*)d_in[1];
    const float* tp   = (const float*)d_in[2];
    const float* ss   = (const float*)d_in[3];
    const float* sa   = (const float*)d_in[4];
    const float* sn   = (const float*)d_in[5];
    const float* W1   = (const float*)d_in[6];
    const float* b1   = (const float*)d_in[7];
    const float* W2   = (const float*)d_in[8];
    const float* b2   = (const float*)d_in[9];
    float* out = (float*)d_out;

    int S = in_sizes[3];          // source_strengths element count
    int T = in_sizes[2] / 3;      // target_points is (T, 3)

    zero_kernel<<<(out_size + 255) / 256, 256>>>(out, out_size);

    dim3 grid((T + TPB - 1) / TPB, (S + SCHUNK - 1) / SCHUNK);
    bh_kernel<<<grid, TPB>>>(refL, sp, tp, ss, sa, sn, W1, b1, W2, b2, out, T, S);
}

// round 3
// speedup vs baseline: 1.4404x; 1.3993x over previous
#include <cuda_runtime.h>

#define TPB 128      // threads per block == targets per block
#define SCHUNK 16    // sources handled per block (grid.y splits S) -> 64 y-blocks
#define NS 4         // sources per thread-iteration = 2 packed f32x2 lanes

typedef unsigned long long ull;

__device__ __forceinline__ ull pack2(float lo, float hi) {
    ull r; asm("mov.b64 %0, {%1, %2};" : "=l"(r) : "f"(lo), "f"(hi)); return r;
}
__device__ __forceinline__ void unpack2(ull v, float& lo, float& hi) {
    asm("mov.b64 {%0, %1}, %2;" : "=f"(lo), "=f"(hi) : "l"(v));
}
__device__ __forceinline__ ull fma2(ull a, ull b, ull c) {
    ull d; asm("fma.rn.f32x2 %0, %1, %2, %3;" : "=l"(d) : "l"(a), "l"(b), "l"(c)); return d;
}
__device__ __forceinline__ ull mul2(ull a, ull b) {
    ull d; asm("mul.rn.f32x2 %0, %1, %2;" : "=l"(d) : "l"(a), "l"(b)); return d;
}
__device__ __forceinline__ float tanh_apx(float x) {
    float y; asm("tanh.approx.f32 %0, %1;" : "=f"(y) : "f"(x)); return y;
}
// silu(a) = a*sigmoid(a) = b + b*tanh(b), b = a/2   (packed, 2 MUFU.TANH)
__device__ __forceinline__ ull silu2(ull a, ull halfp) {
    ull b = mul2(a, halfp);
    float blo, bhi; unpack2(b, blo, bhi);
    ull t = pack2(tanh_apx(blo), tanh_apx(bhi));
    return fma2(b, t, b);
}
// accurate scalar tanh for the epilogue: 1 - 2/(exp(2x)+1)
__device__ __forceinline__ float tanh_fast(float x) {
    float e = __expf(2.0f * x);
    return 1.0f - __fdividef(2.0f, e + 1.0f);
}

struct __align__(16) SrcData {
    float x, y, z, area;       // coords pre-scaled by 1/refL
    float logn, nhx, nhy, nhz; // 0.5*ln(n2), unit normal
    float w, pad0, pad1, pad2; // strength
};

__global__ void __launch_bounds__(256) zero_kernel(float* out, int n) {
    int i = blockIdx.x * blockDim.x + threadIdx.x;
    if (i < n) out[i] = 0.0f;
}

__global__ void __launch_bounds__(TPB, 4) bh_kernel(
    const float* __restrict__ refL,
    const float* __restrict__ sp,
    const float* __restrict__ tp,
    const float* __restrict__ ss,
    const float* __restrict__ sa,
    const float* __restrict__ sn,
    const float* __restrict__ W1,
    const float* __restrict__ b1,
    const float* __restrict__ W2,
    const float* __restrict__ b2,
    float* __restrict__ out,
    int T, int S)
{
    // Per-j weight record: 12 duplicated-packed words, read as 6 LDS.128
    // broadcasts: {w0,w1}{w2,w3}{w4,w5}{w6,b}{v0,v1}{v2,v3}
    __shared__ __align__(16) ull sWj[64][12];
    __shared__ ull sb2d[4];
    __shared__ SrcData ssrc[SCHUNK];

    const int tid = threadIdx.x;
    const float invL = 1.0f / refL[0];

    for (int i = tid; i < 64 * 12; i += TPB) {
        int j = i / 12, k = i % 12;
        float w;
        if (k < 7)       w = W1[k * 64 + j];
        else if (k == 7) w = b1[j];
        else             w = W2[j * 4 + (k - 8)];
        sWj[j][k] = pack2(w, w);
    }
    if (tid < 4) { float w = b2[tid]; sb2d[tid] = pack2(w, w); }

    const int s0 = blockIdx.y * SCHUNK;
    if (tid < SCHUNK) {
        int s = s0 + tid;
        SrcData d;
        if (s < S) {
            float nx = sn[3 * s], ny = sn[3 * s + 1], nz = sn[3 * s + 2];
            float n2 = fmaf(nx, nx, fmaf(ny, ny, nz * nz)) + 1e-16f;
            float invn = rsqrtf(n2);
            d.x = sp[3 * s] * invL;
            d.y = sp[3 * s + 1] * invL;
            d.z = sp[3 * s + 2] * invL;
            d.area = sa[s];
            d.logn = 0.5f * __logf(n2);
            d.nhx = nx * invn; d.nhy = ny * invn; d.nhz = nz * invn;
            d.w = ss[s];
        } else {
            d.x = 0.f; d.y = 0.f; d.z = 0.f; d.area = 0.f;
            d.logn = 0.f; d.nhx = 1.f; d.nhy = 0.f; d.nhz = 0.f;
            d.w = 0.f;  // zero strength -> no contribution
        }
        d.pad0 = d.pad1 = d.pad2 = 0.f;
        ssrc[tid] = d;
    }
    __syncthreads();

    const int t = blockIdx.x * TPB + tid;
    if (t >= T) return;

    const float tx = tp[3 * t] * invL;
    const float ty = tp[3 * t + 1] * invL;
    const float tz = tp[3 * t + 2] * invL;

    const ull halfp = pack2(0.5f, 0.5f);

    float acc0 = 0.f, acc1 = 0.f, acc2 = 0.f, acc3 = 0.f;

    #pragma unroll 1
    for (int sb = 0; sb < SCHUNK; sb += NS) {
        // ---- front: per-source features (scalar), then pack into 2 lanes
        float f0[NS], f1[NS], f2[NS], f3[NS], f4[NS], f5[NS], f6[NS];
        float rx[NS], ry[NS], rz[NS], ir[NS];
        #pragma unroll
        for (int u = 0; u < NS; u++) {
            const SrcData sd = ssrc[sb + u];
            float dx = tx - sd.x, dy = ty - sd.y, dz = tz - sd.z;
            float r2 = fmaf(dx, dx, fmaf(dy, dy, dz * dz)) + 1e-16f;
            float irr = rsqrtf(r2);
            float c = (dx * sd.nhx + dy * sd.nhy + dz * sd.nhz) * irr;
            float c2 = c * c;
            f0[u] = sd.area;
            f1[u] = 0.5f * __logf(r2);
            f2[u] = sd.logn;
            f3[u] = c;
            f4[u] = fmaf(1.5f, c2, -0.5f);
            f5[u] = fmaf(2.5f, c2, -1.5f) * c;
            f6[u] = fmaf(fmaf(4.375f, c2, -3.75f), c2, 0.375f);
            rx[u] = dx; ry[u] = dy; rz[u] = dz; ir[u] = irr;
        }
        ull F0[2], F1[2], F2[2], F3[2], F4[2], F5[2], F6[2];
        ull O0[2], O1[2], O2[2], O3[2];
        #pragma unroll
        for (int l = 0; l < 2; l++) {
            F0[l] = pack2(f0[2*l], f0[2*l+1]);
            F1[l] = pack2(f1[2*l], f1[2*l+1]);
            F2[l] = pack2(f2[2*l], f2[2*l+1]);
            F3[l] = pack2(f3[2*l], f3[2*l+1]);
            F4[l] = pack2(f4[2*l], f4[2*l+1]);
            F5[l] = pack2(f5[2*l], f5[2*l+1]);
            F6[l] = pack2(f6[2*l], f6[2*l+1]);
            O0[l] = sb2d[0]; O1[l] = sb2d[1]; O2[l] = sb2d[2]; O3[l] = sb2d[3];
        }

        // ---- fused MLP: packed f32x2 FMAs, weights via 6 LDS.128 broadcasts
        #pragma unroll 4
        for (int j = 0; j < 64; j++) {
            const ulonglong2* wp = (const ulonglong2*)sWj[j];
            ulonglong2 p0 = wp[0];   // w0, w1
            ulonglong2 p1 = wp[1];   // w2, w3
            ulonglong2 p2 = wp[2];   // w4, w5
            ulonglong2 p3 = wp[3];   // w6, b
            ulonglong2 p4 = wp[4];   // v0, v1
            ulonglong2 p5 = wp[5];   // v2, v3
            #pragma unroll
            for (int l = 0; l < 2; l++) {
                ull a = p3.y;
                a = fma2(F0[l], p0.x, a);
                a = fma2(F1[l], p0.y, a);
                a = fma2(F2[l], p1.x, a);
                a = fma2(F3[l], p1.y, a);
                a = fma2(F4[l], p2.x, a);
                a = fma2(F5[l], p2.y, a);
                a = fma2(F6[l], p3.x, a);
                ull h = silu2(a, halfp);
                O0[l] = fma2(h, p4.x, O0[l]);
                O1[l] = fma2(h, p4.y, O1[l]);
                O2[l] = fma2(h, p5.x, O2[l]);
                O3[l] = fma2(h, p5.y, O3[l]);
            }
        }

        // ---- epilogue: tanh, decay weighting, accumulate
        float o0[NS], o1[NS], o2[NS], o3[NS];
        unpack2(O0[0], o0[0], o0[1]); unpack2(O0[1], o0[2], o0[3]);
        unpack2(O1[0], o1[0], o1[1]); unpack2(O1[1], o1[2], o1[3]);
        unpack2(O2[0], o2[0], o2[1]); unpack2(O2[1], o2[2], o2[3]);
        unpack2(O3[0], o3[0], o3[1]); unpack2(O3[1], o3[2], o3[3]);
        #pragma unroll
        for (int u = 0; u < NS; u++) {
            const SrcData sd = ssrc[sb + u];
            float t0 = tanh_fast(o0[u]);
            float t1 = tanh_fast(o1[u]);
            float t2 = tanh_fast(o2[u]);
            float t3 = tanh_fast(o3[u]);
            float irr = ir[u];
            float wir = sd.w * irr;              // w * inv_r   (scalar decay, D=3)
            acc0 = fmaf(wir, t0, acc0);
            float wv = wir * irr;                // w * inv_r^2 (vector decay)
            float rhx = rx[u] * irr, rhy = ry[u] * irr, rhz = rz[u] * irr;
            float cx = rhy * sd.nhz - rhz * sd.nhy;
            float cy = rhz * sd.nhx - rhx * sd.nhz;
            float cz = rhx * sd.nhy - rhy * sd.nhx;
            acc1 = fmaf(wv, fmaf(t1, rhx, fmaf(t2, sd.nhx, t3 * cx)), acc1);
            acc2 = fmaf(wv, fmaf(t1, rhy, fmaf(t2, sd.nhy, t3 * cy)), acc2);
            acc3 = fmaf(wv, fmaf(t1, rhz, fmaf(t2, sd.nhz, t3 * cz)), acc3);
        }
    }

    atomicAdd(&out[4 * t + 0], acc0);
    atomicAdd(&out[4 * t + 1], acc1);
    atomicAdd(&out[4 * t + 2], acc2);
    atomicAdd(&out[4 * t + 3], acc3);
}

extern "C" void kernel_launch(void* const* d_in, const int* in_sizes, int n_in,
                              void* d_out, int out_size) {
    const float* refL = (const float*)d_in[0];
    const float* sp   = (const float*)d_in[1];
    const float* tp   = (const float*)d_in[2];
    const float* ss   = (const float*)d_in[3];
    const float* sa   = (const float*)d_in[4];
    const float* sn   = (const float*)d_in[5];
    const float* W1   = (const float*)d_in[6];
    const float* b1   = (const float*)d_in[7];
    const float* W2   = (const float*)d_in[8];
    const float* b2   = (const float*)d_in[9];
    float* out = (float*)d_out;

    int S = in_sizes[3];          // source_strengths element count
    int T = in_sizes[2] / 3;      // target_points is (T, 3)

    zero_kernel<<<(out_size + 255) / 256, 256>>>(out, out_size);

    dim3 grid((T + TPB - 1) / TPB, (S + SCHUNK - 1) / SCHUNK);
    bh_kernel<<<grid, TPB>>>(refL, sp, tp, ss, sa, sn, W1, b1, W2, b2, out, T, S);
}

// round 4
// speedup vs baseline: 1.6934x; 1.1756x over previous
#include <cuda_runtime.h>

#define TPB 128      // threads per block == targets per block
#define SCHUNK 8     // sources per block (grid.y splits S)
#define NS 4         // sources per thread-iteration = 2 packed f32x2 lanes
#define SMAX 8192

typedef unsigned long long ull;

__device__ __forceinline__ ull pack2(float lo, float hi) {
    ull r; asm("mov.b64 %0, {%1, %2};" : "=l"(r) : "f"(lo), "f"(hi)); return r;
}
__device__ __forceinline__ void unpack2(ull v, float& lo, float& hi) {
    asm("mov.b64 {%0, %1}, %2;" : "=f"(lo), "=f"(hi) : "l"(v));
}
__device__ __forceinline__ ull fma2(ull a, ull b, ull c) {
    ull d; asm("fma.rn.f32x2 %0, %1, %2, %3;" : "=l"(d) : "l"(a), "l"(b), "l"(c)); return d;
}
__device__ __forceinline__ float tanh_apx(float x) {
    float y; asm("tanh.approx.f32 %0, %1;" : "=f"(y) : "f"(x)); return y;
}
// accurate scalar tanh for the epilogue: 1 - 2/(exp(2x)+1)
__device__ __forceinline__ float tanh_fast(float x) {
    float e = __expf(2.0f * x);
    return 1.0f - __fdividef(2.0f, e + 1.0f);
}

struct __align__(16) SrcData {
    float x, y, z, area;       // coords pre-scaled by 1/refL
    float logn, nhx, nhy, nhz; // 0.5*ln(n2), unit normal
    float w, pad0, pad1, pad2; // strength
};

// ---- device-global scratch (prep results) ----
__device__ SrcData g_src[SMAX];
__device__ float   g_aconst[SMAX * 64];          // per-(source,j) folded constant (pre-halved)
__device__ __align__(16) ull g_wrec[64][10];     // per-j: w1log,q1,q2,q3,q4 (pre-halved) | v0..v3 | pad
__device__ ull g_b2[4];

__global__ void __launch_bounds__(256) zero_kernel(float* out, int n) {
    int i = blockIdx.x * blockDim.x + threadIdx.x;
    if (i < n) out[i] = 0.0f;
}

__global__ void prep_src(const float* __restrict__ refL,
                         const float* __restrict__ sp,
                         const float* __restrict__ ss,
                         const float* __restrict__ sa,
                         const float* __restrict__ sn,
                         int S, int SP) {
    int s = blockIdx.x * blockDim.x + threadIdx.x;
    if (s >= SP) return;
    SrcData d;
    if (s < S) {
        float invL = 1.0f / refL[0];
        float nx = sn[3 * s], ny = sn[3 * s + 1], nz = sn[3 * s + 2];
        float n2 = fmaf(nx, nx, fmaf(ny, ny, nz * nz)) + 1e-16f;
        float invn = rsqrtf(n2);
        d.x = sp[3 * s] * invL;
        d.y = sp[3 * s + 1] * invL;
        d.z = sp[3 * s + 2] * invL;
        d.area = sa[s];
        d.logn = 0.5f * __logf(n2);
        d.nhx = nx * invn; d.nhy = ny * invn; d.nhz = nz * invn;
        d.w = ss[s];
    } else {
        d.x = 0.f; d.y = 0.f; d.z = 0.f; d.area = 0.f;
        d.logn = 0.f; d.nhx = 1.f; d.nhy = 0.f; d.nhz = 0.f;
        d.w = 0.f;
    }
    d.pad0 = d.pad1 = d.pad2 = 0.f;
    g_src[s] = d;
}

// Legendre fold:  w3*P1 + w4*P2 + w5*P3 + w6*P4
//   = (w3-1.5w5)c + (1.5w4-3.75w6)c^2 + 2.5w5 c^3 + 4.375w6 c^4 + (-0.5w4+0.375w6)
__global__ void prep_wrec(const float* __restrict__ W1,
                          const float* __restrict__ b2,
                          const float* __restrict__ W2) {
    int j = threadIdx.x;
    if (j < 64) {
        float w3 = W1[3 * 64 + j], w4 = W1[4 * 64 + j];
        float w5 = W1[5 * 64 + j], w6 = W1[6 * 64 + j];
        float w1log = 0.5f * W1[1 * 64 + j];                 // pre-halved for silu trick
        float q1 = 0.5f * (w3 - 1.5f * w5);
        float q2 = 0.5f * (1.5f * w4 - 3.75f * w6);
        float q3 = 0.5f * (2.5f * w5);
        float q4 = 0.5f * (4.375f * w6);
        g_wrec[j][0] = pack2(w1log, w1log);
        g_wrec[j][1] = pack2(q1, q1);
        g_wrec[j][2] = pack2(q2, q2);
        g_wrec[j][3] = pack2(q3, q3);
        g_wrec[j][4] = pack2(q4, q4);
        #pragma unroll
        for (int k = 0; k < 4; k++) {
            float v = W2[j * 4 + k];
            g_wrec[j][5 + k] = pack2(v, v);
        }
        g_wrec[j][9] = 0ull;
    }
    if (j < 4) { float v = b2[j]; g_b2[j] = pack2(v, v); }
}

__global__ void prep_aconst(const float* __restrict__ W1,
                            const float* __restrict__ b1,
                            int SP) {
    int idx = blockIdx.x * blockDim.x + threadIdx.x;
    if (idx >= SP * 64) return;
    int s = idx >> 6, j = idx & 63;
    float qc = fmaf(-0.5f, W1[4 * 64 + j], 0.375f * W1[6 * 64 + j]);
    float v = b1[j] + qc;
    v = fmaf(g_src[s].area, W1[0 * 64 + j], v);
    v = fmaf(g_src[s].logn, W1[2 * 64 + j], v);
    g_aconst[idx] = 0.5f * v;   // pre-halved
}

__global__ void __launch_bounds__(TPB, 5) bh_kernel(
    const float* __restrict__ refL,
    const float* __restrict__ tp,
    float* __restrict__ out,
    int T)
{
    __shared__ __align__(16) ull sW[64][10];   // 5 KB
    __shared__ ull sA[64][SCHUNK / 2];         // 2 KB  packed aconst pairs
    __shared__ SrcData ssrc[SCHUNK];
    __shared__ ull sb2d[4];

    const int tid = threadIdx.x;
    const int s0 = blockIdx.y * SCHUNK;

    for (int i = tid; i < 64 * 10; i += TPB)
        ((ull*)sW)[i] = ((const ull*)g_wrec)[i];
    for (int i = tid; i < 64 * (SCHUNK / 2); i += TPB) {
        int j = i / (SCHUNK / 2), l = i % (SCHUNK / 2);
        sA[j][l] = pack2(g_aconst[(s0 + 2 * l) * 64 + j],
                         g_aconst[(s0 + 2 * l + 1) * 64 + j]);
    }
    if (tid < SCHUNK) ssrc[tid] = g_src[s0 + tid];
    if (tid < 4) sb2d[tid] = g_b2[tid];
    __syncthreads();

    const int t = blockIdx.x * TPB + tid;
    if (t >= T) return;

    const float invL = 1.0f / refL[0];
    const float tx = tp[3 * t] * invL;
    const float ty = tp[3 * t + 1] * invL;
    const float tz = tp[3 * t + 2] * invL;

    float acc0 = 0.f, acc1 = 0.f, acc2 = 0.f, acc3 = 0.f;

    #pragma unroll 1
    for (int sb = 0; sb < SCHUNK; sb += NS) {
        // ---- front: per-source geometry, pack powers of cos and log r
        float lr[NS], c1[NS], cc2[NS], cc3[NS], cc4[NS];
        float rx[NS], ry[NS], rz[NS], ir[NS];
        #pragma unroll
        for (int u = 0; u < NS; u++) {
            const SrcData sd = ssrc[sb + u];
            float dx = tx - sd.x, dy = ty - sd.y, dz = tz - sd.z;
            float r2 = fmaf(dx, dx, fmaf(dy, dy, fmaf(dz, dz, 1e-16f)));
            float irr = rsqrtf(r2);
            float c = (dx * sd.nhx + dy * sd.nhy + dz * sd.nhz) * irr;
            float c2 = c * c;
            lr[u] = 0.34657359f * __log2f(r2);   // 0.5*ln(r2)
            c1[u] = c;
            cc2[u] = c2;
            cc3[u] = c * c2;
            cc4[u] = c2 * c2;
            rx[u] = dx; ry[u] = dy; rz[u] = dz; ir[u] = irr;
        }
        ull LOGR[2], C[2], C2[2], C3[2], C4[2];
        ull O0[2], O1[2], O2[2], O3[2];
        #pragma unroll
        for (int l = 0; l < 2; l++) {
            LOGR[l] = pack2(lr[2*l], lr[2*l+1]);
            C[l]    = pack2(c1[2*l], c1[2*l+1]);
            C2[l]   = pack2(cc2[2*l], cc2[2*l+1]);
            C3[l]   = pack2(cc3[2*l], cc3[2*l+1]);
            C4[l]   = pack2(cc4[2*l], cc4[2*l+1]);
            O0[l] = sb2d[0]; O1[l] = sb2d[1]; O2[l] = sb2d[2]; O3[l] = sb2d[3];
        }

        const int abase = sb >> 1;   // 0 or 2
        // ---- fused MLP: 10 packed FMAs + 2 MUFU.TANH per j per lane-pair
        #pragma unroll 4
        for (int j = 0; j < 64; j++) {
            const ulonglong2* wp = (const ulonglong2*)&sW[j][0];
            ulonglong2 p0 = wp[0];   // w1log, q1
            ulonglong2 p1 = wp[1];   // q2, q3
            ulonglong2 p2 = wp[2];   // q4, v0
            ulonglong2 p3 = wp[3];   // v1, v2
            ull v3 = sW[j][8];
            ull A0 = sA[j][abase], A1 = sA[j][abase + 1];
            #pragma unroll
            for (int l = 0; l < 2; l++) {
                ull b = fma2(LOGR[l], p0.x, l ? A1 : A0);
                b = fma2(C[l],  p0.y, b);
                b = fma2(C2[l], p1.x, b);
                b = fma2(C3[l], p1.y, b);
                b = fma2(C4[l], p2.x, b);
                // silu(2b) = b + b*tanh(b)  (layer-1 weights pre-halved)
                float blo, bhi; unpack2(b, blo, bhi);
                ull tt = pack2(tanh_apx(blo), tanh_apx(bhi));
                ull h = fma2(b, tt, b);
                O0[l] = fma2(h, p2.y, O0[l]);
                O1[l] = fma2(h, p3.x, O1[l]);
                O2[l] = fma2(h, p3.y, O2[l]);
                O3[l] = fma2(h, v3, O3[l]);
            }
        }

        // ---- epilogue: tanh, decay weighting, accumulate
        float o0[NS], o1[NS], o2[NS], o3[NS];
        unpack2(O0[0], o0[0], o0[1]); unpack2(O0[1], o0[2], o0[3]);
        unpack2(O1[0], o1[0], o1[1]); unpack2(O1[1], o1[2], o1[3]);
        unpack2(O2[0], o2[0], o2[1]); unpack2(O2[1], o2[2], o2[3]);
        unpack2(O3[0], o3[0], o3[1]); unpack2(O3[1], o3[2], o3[3]);
        #pragma unroll
        for (int u = 0; u < NS; u++) {
            const SrcData sd = ssrc[sb + u];
            float t0 = tanh_fast(o0[u]);
            float t1 = tanh_fast(o1[u]);
            float t2 = tanh_fast(o2[u]);
            float t3 = tanh_fast(o3[u]);
            float irr = ir[u];
            float wir = sd.w * irr;              // w * inv_r   (scalar decay, D=3)
            acc0 = fmaf(wir, t0, acc0);
            float wv = wir * irr;                // w * inv_r^2 (vector decay)
            float rhx = rx[u] * irr, rhy = ry[u] * irr, rhz = rz[u] * irr;
            float cx = rhy * sd.nhz - rhz * sd.nhy;
            float cy = rhz * sd.nhx - rhx * sd.nhz;
            float cz = rhx * sd.nhy - rhy * sd.nhx;
            acc1 = fmaf(wv, fmaf(t1, rhx, fmaf(t2, sd.nhx, t3 * cx)), acc1);
            acc2 = fmaf(wv, fmaf(t1, rhy, fmaf(t2, sd.nhy, t3 * cy)), acc2);
            acc3 = fmaf(wv, fmaf(t1, rhz, fmaf(t2, sd.nhz, t3 * cz)), acc3);
        }
    }

    atomicAdd(&out[4 * t + 0], acc0);
    atomicAdd(&out[4 * t + 1], acc1);
    atomicAdd(&out[4 * t + 2], acc2);
    atomicAdd(&out[4 * t + 3], acc3);
}

extern "C" void kernel_launch(void* const* d_in, const int* in_sizes, int n_in,
                              void* d_out, int out_size) {
    const float* refL = (const float*)d_in[0];
    const float* sp   = (const float*)d_in[1];
    const float* tp   = (const float*)d_in[2];
    const float* ss   = (const float*)d_in[3];
    const float* sa   = (const float*)d_in[4];
    const float* sn   = (const float*)d_in[5];
    const float* W1   = (const float*)d_in[6];
    const float* b1   = (const float*)d_in[7];
    const float* W2   = (const float*)d_in[8];
    const float* b2   = (const float*)d_in[9];
    float* out = (float*)d_out;

    int S = in_sizes[3];          // source_strengths element count
    int T = in_sizes[2] / 3;      // target_points is (T, 3)
    int SP = ((S + SCHUNK - 1) / SCHUNK) * SCHUNK;
    if (SP > SMAX) SP = SMAX;

    zero_kernel<<<(out_size + 255) / 256, 256>>>(out, out_size);
    prep_src<<<(SP + 127) / 128, 128>>>(refL, sp, ss, sa, sn, S, SP);
    prep_wrec<<<1, 64>>>(W1, b2, W2);
    prep_aconst<<<(SP * 64 + 255) / 256, 256>>>(W1, b1, SP);

    dim3 grid((T + TPB - 1) / TPB, SP / SCHUNK);
    bh_kernel<<<grid, TPB>>>(refL, tp, out, T);
}